// round 13
// baseline (speedup 1.0000x reference)
#include <cuda_runtime.h>
#include <cuda_fp16.h>
#include <math.h>

#define NB 16
#define NC 512
#define NL 1024
#define NH 8
#define CL_ (NC*NL)
#define BCL_ (NB*CL_)
#define CC (NC*NC)

/* ------------------------------------------------------------------ */
__device__ float g_mu[NB*NL];
__device__ float g_rs[NB*NL];
__device__ __align__(16) __half g_Rh [BCL_];    /* residual, fp16 now */
__device__ __align__(16) __half g_Wh [9*CC];
__device__ __align__(16) __half g_Th [BCL_];
__device__ __align__(16) __half g_Th2[BCL_];
__device__ __align__(16) __half g_Qh [BCL_];
__device__ __align__(16) __half g_KVh[2*BCL_];

/* ------------------------------------------------------------------ */
__global__ void cvt_h_kernel(const float* __restrict__ src,
                             __half* __restrict__ dst, int n4)
{
    int i = blockIdx.x * 256 + threadIdx.x;
    if (i < n4) {
        float4 v = ((const float4*)src)[i];
        ((__half2*)dst)[i*2    ] = __floats2half2_rn(v.x, v.y);
        ((__half2*)dst)[i*2 + 1] = __floats2half2_rn(v.z, v.w);
    }
}

/* ------------------------------------------------------------------ */
/* posenc -> fp16 R (2 elems/thread)                                   */
/* ------------------------------------------------------------------ */
__global__ void posenc_kernel(const float* __restrict__ x, __half* __restrict__ out)
{
    long idx = ((long)blockIdx.x * 256 + threadIdx.x) * 2;
    int l = idx & (NL - 1);
    int c = (idx >> 10) & (NC - 1);
    int i = (c < 256) ? c : (c - 256);
    float inv = expf(-(float)i * 0.036118982f);
    float s0, s1;
    if (c < 256) { s0 = sinf(l * inv); s1 = sinf((l + 1) * inv); }
    else         { s0 = cosf(l * inv); s1 = cosf((l + 1) * inv); }
    float2 xv = *(const float2*)&x[idx];
    *(__half2*)&out[idx] = __floats2half2_rn(xv.x + s0, xv.y + s1);
}

/* ------------------------------------------------------------------ */
__global__ void ln_stats_kernel(const __half* __restrict__ R,
                                float* __restrict__ mu, float* __restrict__ rstd)
{
    int tile = blockIdx.x;
    int b  = tile >> 5;
    int l0 = (tile & 31) << 5;
    int t  = threadIdx.x;
    int lane = t & 31, w = t >> 5;

    const __half* base = R + (long)b * CL_ + l0 + lane;
    float s = 0.f, s2 = 0.f;
    for (int c = w; c < NC; c += 8) {
        float v = __half2float(base[c * NL]);
        s += v; s2 += v * v;
    }
    __shared__ float sh1[8][32], sh2[8][32];
    sh1[w][lane] = s; sh2[w][lane] = s2;
    __syncthreads();
    if (t < 32) {
        float a = 0.f, q = 0.f;
        #pragma unroll
        for (int ww = 0; ww < 8; ww++) { a += sh1[ww][t]; q += sh2[ww][t]; }
        float m   = a * (1.f / NC);
        float var = q * (1.f / NC) - m * m;
        mu  [b * NL + l0 + t] = m;
        rstd[b * NL + l0 + t] = rsqrtf(var + 1e-5f);
    }
}

/* ------------------------------------------------------------------ */
__global__ void ln_apply_kernel(const __half* __restrict__ R,
                                const float* __restrict__ mu,
                                const float* __restrict__ rstd,
                                const float* __restrict__ sc,
                                const float* __restrict__ bi,
                                __half* __restrict__ out)
{
    int idx4 = blockIdx.x * 256 + threadIdx.x;
    long idx = (long)idx4 * 4;
    int l = idx & (NL - 1);
    int c = (idx >> 10) & (NC - 1);
    int b = idx >> 19;

    __half2 v01 = *(const __half2*)&R[idx];
    __half2 v23 = *(const __half2*)&R[idx + 2];
    float4 m  = *(const float4*)&mu  [b * NL + l];
    float4 rr = *(const float4*)&rstd[b * NL + l];
    float s  = sc[c];
    float bb = bi[c];
    float y0 = (__low2float(v01)  - m.x) * rr.x * s + bb;
    float y1 = (__high2float(v01) - m.y) * rr.y * s + bb;
    float y2 = (__low2float(v23)  - m.z) * rr.z * s + bb;
    float y3 = (__high2float(v23) - m.w) * rr.w * s + bb;
    *(__half2*)&out[idx]     = __floats2half2_rn(y0, y1);
    *(__half2*)&out[idx + 2] = __floats2half2_rn(y2, y3);
}

/* ------------------------------------------------------------------ */
__global__ void dwconv_ln_kernel(const __half* __restrict__ R,
                                 const float* __restrict__ mu,
                                 const float* __restrict__ rstd,
                                 const float* __restrict__ sc,
                                 const float* __restrict__ bi,
                                 const float* __restrict__ w7,
                                 __half* __restrict__ T)
{
    int idx = blockIdx.x * 256 + threadIdx.x;
    int l = idx & (NL - 1);
    int c = (idx >> 10) & (NC - 1);
    int b = idx >> 19;

    const __half* r   = R    + (long)b * CL_ + (long)c * NL;
    const float* mub = mu   + b * NL;
    const float* rsb = rstd + b * NL;
    float s  = sc[c];
    float bb = bi[c];
    float acc = 0.f;
    #pragma unroll
    for (int k = 0; k < 7; k++) {
        int ll = l + k - 3;
        if (ll >= 0 && ll < NL) {
            float v = (__half2float(r[ll]) - mub[ll]) * rsb[ll] * s + bb;
            acc += w7[c * 7 + k] * v;
        }
    }
    T[idx] = __float2half(acc);
}

/* ------------------------------------------------------------------ */
#define MMA_F16(d0,d1,d2,d3,a0,a1,a2,a3,b0,b1)                               \
    asm volatile(                                                            \
        "mma.sync.aligned.m16n8k16.row.col.f32.f16.f16.f32 "                 \
        "{%0,%1,%2,%3}, {%4,%5,%6,%7}, {%8,%9}, {%0,%1,%2,%3};\n"            \
        : "+f"(d0), "+f"(d1), "+f"(d2), "+f"(d3)                             \
        : "r"(a0), "r"(a1), "r"(a2), "r"(a3), "r"(b0), "r"(b1))

#define LDSM4T(r0,r1,r2,r3,addr)                                             \
    asm volatile("ldmatrix.sync.aligned.m8n8.x4.trans.shared.b16 "           \
                 "{%0,%1,%2,%3}, [%4];"                                      \
                 : "=r"(r0), "=r"(r1), "=r"(r2), "=r"(r3) : "r"(addr))

#define LDSM4(r0,r1,r2,r3,addr)                                              \
    asm volatile("ldmatrix.sync.aligned.m8n8.x4.shared.b16 "                 \
                 "{%0,%1,%2,%3}, [%4];"                                      \
                 : "=r"(r0), "=r"(r1), "=r"(r2), "=r"(r3) : "r"(addr))

__device__ __forceinline__ void cpa16(unsigned saddr, const void* gaddr)
{
    asm volatile("cp.async.cg.shared.global [%0], [%1], 16;\n"
                 :: "r"(saddr), "l"(gaddr));
}

/* ------------------------------------------------------------------ */
/* fp16 batched GEMM (round-12 mainloop); residual is fp16 now         */
/* ------------------------------------------------------------------ */
#define SAH 40
#define SBH 136
#define ASZB (128*SAH*2)
#define BSZB (32*SBH*2)
#define STAGES 4
#define GEMM_SMEM (STAGES*(ASZB+BSZB))

template<bool RELU, bool RES, bool BIAS, bool OUTH>
__global__ void __launch_bounds__(256, 2)
gemm_h_kernel(const __half* __restrict__ W,
              const __half* __restrict__ X,
              void*                      Yv,
              const float* __restrict__ bias,
              const __half*             res,
              long bsX, long bsY, long bsRes, float scale)
{
    const int Kd = NC;
    const int NT = Kd / 32;
    int b  = blockIdx.z;
    int n0 = blockIdx.x * 128;
    int m0 = blockIdx.y * 128;

    const __half* Xb   = X + (long)b * bsX;
    const __half* Resb = RES ? (res + (long)b * bsRes) : (const __half*)0;

    extern __shared__ __half gsm[];
    unsigned saA = (unsigned)__cvta_generic_to_shared(gsm);
    unsigned saB = saA + STAGES * ASZB;

    int t    = threadIdx.x;
    int lane = t & 31, w = t >> 5;
    int g    = lane >> 2, tig = lane & 3;
    int wm   = (w >> 2) * 64;
    int wn   = (w & 3) * 32;

    int rA  = t & 127;
    int cAh = (t >> 7) * 8;
    int kB  = t >> 3;
    int cBh = (t & 7) * 8;

    unsigned sA = saA + (rA * SAH + cAh) * 2;
    unsigned sB = saB + (kB * SBH + cBh) * 2;
    const __half* gA = W  + (long)(m0 + rA) * Kd + cAh;
    const __half* gB = Xb + (long)kB * NL + n0 + cBh;

    int rowk = (lane & 7) + ((lane >> 3) & 1) * 8;
    int coff = ((lane >> 4) & 1) * 8;

    float acc[4][4][4];
    #pragma unroll
    for (int mt = 0; mt < 4; mt++)
        #pragma unroll
        for (int nt = 0; nt < 4; nt++)
            #pragma unroll
            for (int i = 0; i < 4; i++) acc[mt][nt][i] = 0.f;

#define ISSUE(KT, STG) {                                                  \
        unsigned a_ = sA + (STG) * ASZB;                                  \
        const __half* ga_ = gA + (KT) * 32;                               \
        cpa16(a_,      ga_);                                              \
        cpa16(a_ + 32, ga_ + 16);                                         \
        unsigned b_ = sB + (STG) * BSZB;                                  \
        const __half* gb_ = gB + (long)(KT) * 32 * NL;                    \
        cpa16(b_,       gb_);                                             \
        cpa16(b_ + 128, gb_ + 64);                                        \
        asm volatile("cp.async.commit_group;\n" ::: "memory"); }

    ISSUE(0, 0);
    ISSUE(1, 1);
    ISSUE(2, 2);

    for (int kt = 0; kt < NT; kt++) {
        asm volatile("cp.async.wait_group 2;\n" ::: "memory");
        __syncthreads();

        int cur = kt & 3;
        unsigned aBase = saA + cur * ASZB;
        unsigned bBase = saB + cur * BSZB;

        #pragma unroll
        for (int kk = 0; kk < 32; kk += 16) {
            unsigned bf[4][2];
            unsigned bb = bBase + (unsigned)(((kk + rowk) * SBH + wn + coff) * 2);
            LDSM4T(bf[0][0], bf[0][1], bf[1][0], bf[1][1], bb);
            LDSM4T(bf[2][0], bf[2][1], bf[3][0], bf[3][1], bb + 32);

            #pragma unroll
            for (int mt = 0; mt < 4; mt++) {
                unsigned a0, a1, a2, a3;
                LDSM4(a0, a1, a2, a3,
                      aBase + (unsigned)(((wm + mt * 16 + rowk) * SAH + kk + coff) * 2));
                #pragma unroll
                for (int nt = 0; nt < 4; nt++)
                    MMA_F16(acc[mt][nt][0], acc[mt][nt][1],
                            acc[mt][nt][2], acc[mt][nt][3],
                            a0, a1, a2, a3, bf[nt][0], bf[nt][1]);
            }
        }

        if (kt + 3 < NT) {
            ISSUE(kt + 3, (kt + 3) & 3);
        } else {
            asm volatile("cp.async.commit_group;\n" ::: "memory");
        }
    }
#undef ISSUE

    /* epilogue */
    #pragma unroll
    for (int mt = 0; mt < 4; mt++) {
        int r0 = m0 + wm + mt * 16 + g;
        int r1 = r0 + 8;
        float bv0 = BIAS ? bias[r0] : 0.f;
        float bv1 = BIAS ? bias[r1] : 0.f;
        #pragma unroll
        for (int nt = 0; nt < 4; nt++) {
            int cn = n0 + wn + nt * 8 + 2 * tig;
            float2 y0, y1;
            y0.x = acc[mt][nt][0] + bv0; y0.y = acc[mt][nt][1] + bv0;
            y1.x = acc[mt][nt][2] + bv1; y1.y = acc[mt][nt][3] + bv1;
            if (RELU) {
                y0.x = fmaxf(y0.x, 0.f); y0.y = fmaxf(y0.y, 0.f);
                y1.x = fmaxf(y1.x, 0.f); y1.y = fmaxf(y1.y, 0.f);
            }
            y0.x *= scale; y0.y *= scale;
            y1.x *= scale; y1.y *= scale;
            if (RES) {
                __half2 rr0 = *(const __half2*)&Resb[(long)r0 * NL + cn];
                __half2 rr1 = *(const __half2*)&Resb[(long)r1 * NL + cn];
                y0.x += __low2float(rr0); y0.y += __high2float(rr0);
                y1.x += __low2float(rr1); y1.y += __high2float(rr1);
            }
            if (OUTH) {
                __half* Yb = (__half*)Yv + (long)b * bsY;
                *(__half2*)&Yb[(long)r0 * NL + cn] = __floats2half2_rn(y0.x, y0.y);
                *(__half2*)&Yb[(long)r1 * NL + cn] = __floats2half2_rn(y1.x, y1.y);
            } else {
                float* Yb = (float*)Yv + (long)b * bsY;
                *(float2*)&Yb[(long)r0 * NL + cn] = y0;
                *(float2*)&Yb[(long)r1 * NL + cn] = y1;
            }
        }
    }
}

/* ------------------------------------------------------------------ */
/* fp16 flash attention; residual R in fp16                            */
/* ------------------------------------------------------------------ */
#define HS 72
#define QB (64*HS*2)
#define KVB (2*64*HS*2)
#define ATTN_SMEM (QB + 2*KVB)

__global__ void __launch_bounds__(128, 4)
attn_h_kernel(const __half* __restrict__ Q,
              const __half* __restrict__ KV,
              __half* R)
{
    extern __shared__ __half smh[];
    unsigned saQ = (unsigned)__cvta_generic_to_shared(smh);
    __shared__ float corrS[64];

    int qt = blockIdx.x, h = blockIdx.y, b = blockIdx.z;
    int q0 = qt * 64;
    int t    = threadIdx.x;
    int lane = t & 31, w = t >> 5;
    int g    = lane >> 2, tig = lane & 3;
    int wq   = w * 16;

    const __half* Qb = Q  + (long)b * CL_     + (long)(h * 64) * NL + q0;
    const __half* Kb = KV + (long)b * 2 * CL_ + (long)(h * 64) * NL;
    const __half* Vb = KV + (long)b * 2 * CL_ + (long)(512 + h * 64) * NL;

    int ddA = (lane & 7) + ((lane >> 4) & 1) * 8;
    int qqA = wq + ((lane >> 3) & 1) * 8;
    int rowk = (lane & 7) + ((lane >> 3) & 1) * 8;
    int coff = ((lane >> 4) & 1) * 8;

    int dcp = t >> 3;
    int ccp = (t & 7) * 8;

#define ISSUE_KV(KT, BF) {                                                   \
        unsigned kb_ = saQ + QB + (BF) * KVB;                                \
        unsigned vb_ = kb_ + 64 * HS * 2;                                    \
        const __half* gk_ = Kb + (KT) * 64 + ccp;                            \
        const __half* gv_ = Vb + (KT) * 64 + ccp;                            \
        _Pragma("unroll")                                                    \
        for (int i4 = 0; i4 < 4; i4++) {                                     \
            int d_ = i4 * 16 + dcp;                                          \
            cpa16(kb_ + (d_ * HS + ccp) * 2, gk_ + (long)d_ * NL);           \
            cpa16(vb_ + (d_ * HS + ccp) * 2, gv_ + (long)d_ * NL);           \
        }                                                                    \
        asm volatile("cp.async.commit_group;\n" ::: "memory"); }

    ISSUE_KV(0, 0);

    #pragma unroll
    for (int i4 = 0; i4 < 4; i4++) {
        int d_ = i4 * 16 + dcp;
        *(uint4*)&smh[d_ * HS + ccp] = *(const uint4*)&Qb[(long)d_ * NL + ccp];
    }

    float mlo = -1e30f, mhi = -1e30f, llo = 0.f, lhi = 0.f;
    float of[8][4];
    #pragma unroll
    for (int nt = 0; nt < 8; nt++)
        #pragma unroll
        for (int i = 0; i < 4; i++) of[nt][i] = 0.f;

    for (int it = 0; it < 16; it++) {
        asm volatile("cp.async.wait_group 0;\n" ::: "memory");
        __syncthreads();

        int cur = it & 1;
        unsigned saK = saQ + QB + cur * KVB;
        __half*  Ksm = smh + (QB / 2) + cur * (KVB / 2);
        __half*  Vsm = Ksm + 64 * HS;

        if (it + 1 < 16) ISSUE_KV(it + 1, cur ^ 1);

        float sf[8][4];
        #pragma unroll
        for (int nt = 0; nt < 8; nt++)
            #pragma unroll
            for (int i = 0; i < 4; i++) sf[nt][i] = 0.f;

        #pragma unroll
        for (int kk = 0; kk < 64; kk += 16) {
            unsigned a0, a1, a2, a3;
            LDSM4T(a0, a1, a2, a3, saQ + (unsigned)(((kk + ddA) * HS + qqA) * 2));
            unsigned bf[8][2];
            #pragma unroll
            for (int n2 = 0; n2 < 4; n2++)
                LDSM4T(bf[2*n2][0], bf[2*n2][1], bf[2*n2+1][0], bf[2*n2+1][1],
                       saK + (unsigned)(((kk + rowk) * HS + n2 * 16 + coff) * 2));
            #pragma unroll
            for (int nt = 0; nt < 8; nt++)
                MMA_F16(sf[nt][0], sf[nt][1], sf[nt][2], sf[nt][3],
                        a0, a1, a2, a3, bf[nt][0], bf[nt][1]);
        }

        float mx_lo = -1e30f, mx_hi = -1e30f;
        #pragma unroll
        for (int nt = 0; nt < 8; nt++) {
            mx_lo = fmaxf(mx_lo, fmaxf(sf[nt][0], sf[nt][1]));
            mx_hi = fmaxf(mx_hi, fmaxf(sf[nt][2], sf[nt][3]));
        }
        mx_lo = fmaxf(mx_lo, __shfl_xor_sync(0xffffffffu, mx_lo, 1));
        mx_lo = fmaxf(mx_lo, __shfl_xor_sync(0xffffffffu, mx_lo, 2));
        mx_hi = fmaxf(mx_hi, __shfl_xor_sync(0xffffffffu, mx_hi, 1));
        mx_hi = fmaxf(mx_hi, __shfl_xor_sync(0xffffffffu, mx_hi, 2));

        float mn_lo = fmaxf(mlo, mx_lo);
        float mn_hi = fmaxf(mhi, mx_hi);
        float cr_lo = __expf(mlo - mn_lo);
        float cr_hi = __expf(mhi - mn_hi);
        mlo = mn_lo; mhi = mn_hi;

        float ps_lo = 0.f, ps_hi = 0.f;
        #pragma unroll
        for (int nt = 0; nt < 8; nt++) {
            sf[nt][0] = __expf(sf[nt][0] - mn_lo);
            sf[nt][1] = __expf(sf[nt][1] - mn_lo);
            sf[nt][2] = __expf(sf[nt][2] - mn_hi);
            sf[nt][3] = __expf(sf[nt][3] - mn_hi);
            ps_lo += sf[nt][0] + sf[nt][1];
            ps_hi += sf[nt][2] + sf[nt][3];
        }
        ps_lo += __shfl_xor_sync(0xffffffffu, ps_lo, 1);
        ps_lo += __shfl_xor_sync(0xffffffffu, ps_lo, 2);
        ps_hi += __shfl_xor_sync(0xffffffffu, ps_hi, 1);
        ps_hi += __shfl_xor_sync(0xffffffffu, ps_hi, 2);
        llo = llo * cr_lo + ps_lo;
        lhi = lhi * cr_hi + ps_hi;

        if (tig == 0) {
            corrS[wq + g]     = cr_lo;
            corrS[wq + g + 8] = cr_hi;
        }
        __syncthreads();

        #pragma unroll
        for (int nt = 0; nt < 8; nt++) {
            int c0 = nt * 8 + 2 * tig;
            *(__half2*)&Ksm[(wq + g    ) * HS + c0] = __floats2half2_rn(sf[nt][0], sf[nt][1]);
            *(__half2*)&Ksm[(wq + g + 8) * HS + c0] = __floats2half2_rn(sf[nt][2], sf[nt][3]);
        }
        __syncthreads();

        #pragma unroll
        for (int nt = 0; nt < 8; nt++) {
            float c0 = corrS[nt * 8 + 2 * tig];
            float c1 = corrS[nt * 8 + 2 * tig + 1];
            of[nt][0] *= c0; of[nt][1] *= c1;
            of[nt][2] *= c0; of[nt][3] *= c1;
        }

        #pragma unroll
        for (int kk = 0; kk < 64; kk += 16) {
            unsigned a0 = *(const unsigned*)&Vsm[(wq + g    ) * HS + kk + 2*tig];
            unsigned a1 = *(const unsigned*)&Vsm[(wq + g + 8) * HS + kk + 2*tig];
            unsigned a2 = *(const unsigned*)&Vsm[(wq + g    ) * HS + kk + 2*tig + 8];
            unsigned a3 = *(const unsigned*)&Vsm[(wq + g + 8) * HS + kk + 2*tig + 8];
            #pragma unroll
            for (int nt = 0; nt < 8; nt++) {
                unsigned b0 = *(const unsigned*)&Ksm[(nt * 8 + g) * HS + kk + 2*tig];
                unsigned b1 = *(const unsigned*)&Ksm[(nt * 8 + g) * HS + kk + 2*tig + 8];
                MMA_F16(of[nt][0], of[nt][1], of[nt][2], of[nt][3],
                        a0, a1, a2, a3, b0, b1);
            }
        }
    }
#undef ISSUE_KV

    __syncthreads();
    if (tig == 0) {
        corrS[wq + g]     = 1.f / llo;
        corrS[wq + g + 8] = 1.f / lhi;
    }
    __syncthreads();

    __half* Rb = R + (long)b * CL_ + (long)(h * 64) * NL;
    #pragma unroll
    for (int nt = 0; nt < 8; nt++) {
        float i0 = corrS[nt * 8 + 2 * tig];
        float i1 = corrS[nt * 8 + 2 * tig + 1];
        int cn = q0 + nt * 8 + 2 * tig;
        int r0 = wq + g, r1 = wq + g + 8;
        __half2 rr0 = *(const __half2*)&Rb[(long)r0 * NL + cn];
        __half2 rr1 = *(const __half2*)&Rb[(long)r1 * NL + cn];
        *(__half2*)&Rb[(long)r0 * NL + cn] =
            __floats2half2_rn(of[nt][0] * i0 + __low2float(rr0),
                              of[nt][1] * i1 + __high2float(rr0));
        *(__half2*)&Rb[(long)r1 * NL + cn] =
            __floats2half2_rn(of[nt][2] * i0 + __low2float(rr1),
                              of[nt][3] * i1 + __high2float(rr1));
    }
}

/* ------------------------------------------------------------------ */
extern "C" void kernel_launch(void* const* d_in, const int* in_sizes, int n_in,
                              void* d_out, int out_size)
{
    const float* x    = (const float*)d_in[0];
    const float* ncs  = (const float*)d_in[4];
    const float* ncb  = (const float*)d_in[5];
    const float* dw   = (const float*)d_in[6];
    const float* pww  = (const float*)d_in[7];
    const float* pwb  = (const float*)d_in[8];
    const float* ln1s = (const float*)d_in[9];
    const float* ln1b = (const float*)d_in[10];
    const float* ln2s = (const float*)d_in[11];
    const float* ln2b = (const float*)d_in[12];
    const float* wkv  = (const float*)d_in[13];
    const float* wq   = (const float*)d_in[14];
    const float* f1w  = (const float*)d_in[15];
    const float* f1b  = (const float*)d_in[16];
    const float* f2w  = (const float*)d_in[17];
    const float* f2b  = (const float*)d_in[18];
    float* out = (float*)d_out;

    float *mu, *rs;
    __half *Rh, *Wh, *Th, *Th2, *Qh, *KVh;
    cudaGetSymbolAddress((void**)&mu,  g_mu);
    cudaGetSymbolAddress((void**)&rs,  g_rs);
    cudaGetSymbolAddress((void**)&Rh,  g_Rh);
    cudaGetSymbolAddress((void**)&Wh,  g_Wh);
    cudaGetSymbolAddress((void**)&Th,  g_Th);
    cudaGetSymbolAddress((void**)&Th2, g_Th2);
    cudaGetSymbolAddress((void**)&Qh,  g_Qh);
    cudaGetSymbolAddress((void**)&KVh, g_KVh);

    cudaFuncSetAttribute(gemm_h_kernel<true,  true,  true,  true >, cudaFuncAttributeMaxDynamicSharedMemorySize, GEMM_SMEM);
    cudaFuncSetAttribute(gemm_h_kernel<false, false, false, true >, cudaFuncAttributeMaxDynamicSharedMemorySize, GEMM_SMEM);
    cudaFuncSetAttribute(gemm_h_kernel<true,  false, true,  true >, cudaFuncAttributeMaxDynamicSharedMemorySize, GEMM_SMEM);
    cudaFuncSetAttribute(gemm_h_kernel<false, true,  true,  false>, cudaFuncAttributeMaxDynamicSharedMemorySize, GEMM_SMEM);
    cudaFuncSetAttribute(attn_h_kernel, cudaFuncAttributeMaxDynamicSharedMemorySize, ATTN_SMEM);

    dim3 blk(256);

    cvt_h_kernel<<<(4*CC/4 + 255)/256, blk>>>(pww, Wh,          4*CC/4);
    cvt_h_kernel<<<(2*CC/4 + 255)/256, blk>>>(wkv, Wh + 4*CC,   2*CC/4);
    cvt_h_kernel<<<(CC/4   + 255)/256, blk>>>(wq,  Wh + 6*CC,   CC/4);
    cvt_h_kernel<<<(CC/4   + 255)/256, blk>>>(f1w, Wh + 7*CC,   CC/4);
    cvt_h_kernel<<<(CC/4   + 255)/256, blk>>>(f2w, Wh + 8*CC,   CC/4);

    posenc_kernel<<<BCL_ / 512, blk>>>(x, Rh);

    for (int i = 0; i < 4; i++) {
        ln_stats_kernel<<<512, blk>>>(Rh, mu, rs);
        dwconv_ln_kernel<<<BCL_ / 256, blk>>>(Rh, mu, rs,
                                              ncs + i * NC, ncb + i * NC,
                                              dw + (long)i * NC * 7, Th);
        gemm_h_kernel<true, true, true, true><<<dim3(8, 4, NB), blk, GEMM_SMEM>>>(
            Wh + (long)i * CC, Th, Rh, pwb + i * NC, Rh, CL_, CL_, CL_, 1.f);
    }

    /* attention */
    ln_stats_kernel<<<512, blk>>>(Rh, mu, rs);
    ln_apply_kernel<<<BCL_ / 1024, blk>>>(Rh, mu, rs, ln1s, ln1b, Th);
    gemm_h_kernel<false, false, false, true><<<dim3(8, 8, NB), blk, GEMM_SMEM>>>(
        Wh + 4*CC, Th, KVh, 0, 0, CL_, 2 * CL_, 0, 1.f);
    gemm_h_kernel<false, false, false, true><<<dim3(8, 4, NB), blk, GEMM_SMEM>>>(
        Wh + 6*CC, Th, Qh, 0, 0, CL_, CL_, 0, 0.125f);

    attn_h_kernel<<<dim3(16, NH, NB), dim3(128), ATTN_SMEM>>>(Qh, KVh, Rh);

    /* ffn */
    ln_stats_kernel<<<512, blk>>>(Rh, mu, rs);
    ln_apply_kernel<<<BCL_ / 1024, blk>>>(Rh, mu, rs, ln2s, ln2b, Th);
    gemm_h_kernel<true, false, true, true><<<dim3(8, 4, NB), blk, GEMM_SMEM>>>(
        Wh + 7*CC, Th, Th2, f1b, 0, CL_, CL_, 0, 1.f);
    gemm_h_kernel<false, true, true, false><<<dim3(8, 4, NB), blk, GEMM_SMEM>>>(
        Wh + 8*CC, Th2, out, f2b, Rh, CL_, CL_, CL_, 1.f);
}

// round 14
// speedup vs baseline: 1.2525x; 1.2525x over previous
#include <cuda_runtime.h>
#include <cuda_fp16.h>
#include <math.h>

#define NB 16
#define NC 512
#define NL 1024
#define NH 8
#define CL_ (NC*NL)
#define BCL_ (NB*CL_)
#define CC (NC*NC)

/* ------------------------------------------------------------------ */
__device__ float g_R [BCL_];
__device__ __align__(16) __half g_Wh [9*CC];
__device__ __align__(16) __half g_Th [BCL_];
__device__ __align__(16) __half g_Th2[BCL_];
__device__ __align__(16) __half g_Qh [BCL_];
__device__ __align__(16) __half g_KVh[2*BCL_];

/* ------------------------------------------------------------------ */
__global__ void cvt_h_kernel(const float* __restrict__ src,
                             __half* __restrict__ dst, int n4)
{
    int i = blockIdx.x * 256 + threadIdx.x;
    if (i < n4) {
        float4 v = ((const float4*)src)[i];
        ((__half2*)dst)[i*2    ] = __floats2half2_rn(v.x, v.y);
        ((__half2*)dst)[i*2 + 1] = __floats2half2_rn(v.z, v.w);
    }
}

/* ------------------------------------------------------------------ */
__global__ void posenc_kernel(const float* __restrict__ x, float* __restrict__ out)
{
    int idx = blockIdx.x * 256 + threadIdx.x;
    int l = idx & (NL - 1);
    int c = (idx >> 10) & (NC - 1);
    int i = (c < 256) ? c : (c - 256);
    float inv = expf(-(float)i * 0.036118982f);
    float arg = (float)l * inv;
    float sig = (c < 256) ? sinf(arg) : cosf(arg);
    out[idx] = x[idx] + sig;
}

/* ------------------------------------------------------------------ */
/* helper: per-block LN stats for 32 l's (lane = l), warps split c     */
/* ------------------------------------------------------------------ */
__device__ __forceinline__ void block_stats32(const float* __restrict__ Rb,
                                              int l0, int t,
                                              float* smu, float* srs, int joff)
{
    int lane = t & 31, w = t >> 5;
    const float* base = Rb + l0 + lane;
    float s = 0.f, s2 = 0.f;
    for (int c = w; c < NC; c += 8) {
        float v = base[c * NL];
        s += v; s2 += v * v;
    }
    __shared__ float sh1[8][33], sh2[8][33];
    sh1[w][lane] = s; sh2[w][lane] = s2;
    __syncthreads();
    if (t < 32) {
        float a = 0.f, q = 0.f;
        #pragma unroll
        for (int ww = 0; ww < 8; ww++) { a += sh1[ww][t]; q += sh2[ww][t]; }
        float m   = a * (1.f / NC);
        float var = q * (1.f / NC) - m * m;
        smu[joff + t] = m;
        srs[joff + t] = rsqrtf(var + 1e-5f);
    }
}

/* ------------------------------------------------------------------ */
/* fused LN-stats + LN-apply -> fp16                                   */
/* block = (b, 32 l's); phase1 stats, phase2 apply                     */
/* ------------------------------------------------------------------ */
__global__ void __launch_bounds__(256, 4)
ln_fused_kernel(const float* __restrict__ R,
                const float* __restrict__ sc,
                const float* __restrict__ bi,
                __half* __restrict__ out)
{
    int tile = blockIdx.x;
    int b  = tile >> 5;
    int l0 = (tile & 31) << 5;
    int t  = threadIdx.x;

    __shared__ float smu[32], srs[32];
    const float* Rb = R + (long)b * CL_;
    block_stats32(Rb, l0, t, smu, srs, 0);
    __syncthreads();

    __half* ob = (__half*)out + (long)b * CL_;
    for (int i = t; i < NC * 16; i += 256) {
        int c  = i >> 4;
        int lj = (i & 15) * 2;
        long off = (long)c * NL + l0 + lj;
        float2 v = *(const float2*)&Rb[off];
        float s  = sc[c], bb = bi[c];
        float y0 = (v.x - smu[lj])     * srs[lj]     * s + bb;
        float y1 = (v.y - smu[lj + 1]) * srs[lj + 1] * s + bb;
        *(__half2*)&ob[off] = __floats2half2_rn(y0, y1);
    }
}

/* ------------------------------------------------------------------ */
/* fused LN-stats + dwconv -> fp16                                     */
/* block = (b, 32 l's); stats for 38 l's incl. halo                    */
/* ------------------------------------------------------------------ */
__global__ void __launch_bounds__(256, 4)
dwconv_f_kernel(const float* __restrict__ R,
                const float* __restrict__ sc,
                const float* __restrict__ bi,
                const float* __restrict__ w7,
                __half* __restrict__ T)
{
    int tile = blockIdx.x;
    int b  = tile >> 5;
    int l0 = (tile & 31) << 5;
    int t  = threadIdx.x;
    int lane = t & 31, w = t >> 5;

    __shared__ float smu[38], srs[38];     /* j = l - (l0-3) : 0..37 */
    const float* Rb = R + (long)b * CL_;

    /* main 32 stats -> j 3..34 */
    block_stats32(Rb, l0, t, smu, srs, 3);

    /* halo stats: warps 1..6, one l each */
    if (w >= 1 && w <= 6) {
        int li = (w <= 3) ? (l0 - 4 + w) : (l0 + 28 + w);
        if (li >= 0 && li < NL) {
            const float* p = Rb + li;
            float a = 0.f, q = 0.f;
            for (int c = lane; c < NC; c += 32) {
                float v = p[c * NL];
                a += v; q += v * v;
            }
            #pragma unroll
            for (int off = 16; off > 0; off >>= 1) {
                a += __shfl_xor_sync(0xffffffffu, a, off);
                q += __shfl_xor_sync(0xffffffffu, q, off);
            }
            if (lane == 0) {
                float m   = a * (1.f / NC);
                float var = q * (1.f / NC) - m * m;
                int j = li - l0 + 3;
                smu[j] = m;
                srs[j] = rsqrtf(var + 1e-5f);
            }
        }
    }
    __syncthreads();

    __half* Tb = (__half*)T + (long)b * CL_;
    for (int i = t; i < NC * 32; i += 256) {
        int c = i >> 5;
        int l = l0 + (i & 31);
        const float* r = Rb + (long)c * NL;
        float s  = sc[c], bb = bi[c];
        float acc = 0.f;
        #pragma unroll
        for (int k = 0; k < 7; k++) {
            int ll = l + k - 3;
            if (ll >= 0 && ll < NL) {
                int j = ll - l0 + 3;
                float v = (r[ll] - smu[j]) * srs[j] * s + bb;
                acc += w7[c * 7 + k] * v;
            }
        }
        Tb[(long)c * NL + l] = __float2half(acc);
    }
}

/* ------------------------------------------------------------------ */
#define MMA_F16(d0,d1,d2,d3,a0,a1,a2,a3,b0,b1)                               \
    asm volatile(                                                            \
        "mma.sync.aligned.m16n8k16.row.col.f32.f16.f16.f32 "                 \
        "{%0,%1,%2,%3}, {%4,%5,%6,%7}, {%8,%9}, {%0,%1,%2,%3};\n"            \
        : "+f"(d0), "+f"(d1), "+f"(d2), "+f"(d3)                             \
        : "r"(a0), "r"(a1), "r"(a2), "r"(a3), "r"(b0), "r"(b1))

#define LDSM4T(r0,r1,r2,r3,addr)                                             \
    asm volatile("ldmatrix.sync.aligned.m8n8.x4.trans.shared.b16 "           \
                 "{%0,%1,%2,%3}, [%4];"                                      \
                 : "=r"(r0), "=r"(r1), "=r"(r2), "=r"(r3) : "r"(addr))

#define LDSM4(r0,r1,r2,r3,addr)                                              \
    asm volatile("ldmatrix.sync.aligned.m8n8.x4.shared.b16 "                 \
                 "{%0,%1,%2,%3}, [%4];"                                      \
                 : "=r"(r0), "=r"(r1), "=r"(r2), "=r"(r3) : "r"(addr))

__device__ __forceinline__ void cpa16(unsigned saddr, const void* gaddr)
{
    asm volatile("cp.async.cg.shared.global [%0], [%1], 16;\n"
                 :: "r"(saddr), "l"(gaddr));
}

/* ------------------------------------------------------------------ */
/* fp16 batched GEMM (round-12, passing): k-step 32, 4-stage cp.async  */
/* ------------------------------------------------------------------ */
#define SAH 40
#define SBH 136
#define ASZB (128*SAH*2)
#define BSZB (32*SBH*2)
#define STAGES 4
#define GEMM_SMEM (STAGES*(ASZB+BSZB))

template<bool RELU, bool RES, bool BIAS, bool OUTH>
__global__ void __launch_bounds__(256, 2)
gemm_h_kernel(const __half* __restrict__ W,
              const __half* __restrict__ X,
              void*                      Yv,
              const float* __restrict__ bias,
              const float*              res,
              long bsX, long bsY, long bsRes, float scale)
{
    const int Kd = NC;
    const int NT = Kd / 32;
    int b  = blockIdx.z;
    int n0 = blockIdx.x * 128;
    int m0 = blockIdx.y * 128;

    const __half* Xb   = X + (long)b * bsX;
    const float*  Resb = RES ? (res + (long)b * bsRes) : (const float*)0;

    extern __shared__ __half gsm[];
    unsigned saA = (unsigned)__cvta_generic_to_shared(gsm);
    unsigned saB = saA + STAGES * ASZB;

    int t    = threadIdx.x;
    int lane = t & 31, w = t >> 5;
    int g    = lane >> 2, tig = lane & 3;
    int wm   = (w >> 2) * 64;
    int wn   = (w & 3) * 32;

    int rA  = t & 127;
    int cAh = (t >> 7) * 8;
    int kB  = t >> 3;
    int cBh = (t & 7) * 8;

    unsigned sA = saA + (rA * SAH + cAh) * 2;
    unsigned sB = saB + (kB * SBH + cBh) * 2;
    const __half* gA = W  + (long)(m0 + rA) * Kd + cAh;
    const __half* gB = Xb + (long)kB * NL + n0 + cBh;

    int rowk = (lane & 7) + ((lane >> 3) & 1) * 8;
    int coff = ((lane >> 4) & 1) * 8;

    float acc[4][4][4];
    #pragma unroll
    for (int mt = 0; mt < 4; mt++)
        #pragma unroll
        for (int nt = 0; nt < 4; nt++)
            #pragma unroll
            for (int i = 0; i < 4; i++) acc[mt][nt][i] = 0.f;

#define ISSUE(KT, STG) {                                                  \
        unsigned a_ = sA + (STG) * ASZB;                                  \
        const __half* ga_ = gA + (KT) * 32;                               \
        cpa16(a_,      ga_);                                              \
        cpa16(a_ + 32, ga_ + 16);                                         \
        unsigned b_ = sB + (STG) * BSZB;                                  \
        const __half* gb_ = gB + (long)(KT) * 32 * NL;                    \
        cpa16(b_,       gb_);                                             \
        cpa16(b_ + 128, gb_ + 64);                                        \
        asm volatile("cp.async.commit_group;\n" ::: "memory"); }

    ISSUE(0, 0);
    ISSUE(1, 1);
    ISSUE(2, 2);

    for (int kt = 0; kt < NT; kt++) {
        asm volatile("cp.async.wait_group 2;\n" ::: "memory");
        __syncthreads();

        int cur = kt & 3;
        unsigned aBase = saA + cur * ASZB;
        unsigned bBase = saB + cur * BSZB;

        #pragma unroll
        for (int kk = 0; kk < 32; kk += 16) {
            unsigned bf[4][2];
            unsigned bb = bBase + (unsigned)(((kk + rowk) * SBH + wn + coff) * 2);
            LDSM4T(bf[0][0], bf[0][1], bf[1][0], bf[1][1], bb);
            LDSM4T(bf[2][0], bf[2][1], bf[3][0], bf[3][1], bb + 32);

            #pragma unroll
            for (int mt = 0; mt < 4; mt++) {
                unsigned a0, a1, a2, a3;
                LDSM4(a0, a1, a2, a3,
                      aBase + (unsigned)(((wm + mt * 16 + rowk) * SAH + kk + coff) * 2));
                #pragma unroll
                for (int nt = 0; nt < 4; nt++)
                    MMA_F16(acc[mt][nt][0], acc[mt][nt][1],
                            acc[mt][nt][2], acc[mt][nt][3],
                            a0, a1, a2, a3, bf[nt][0], bf[nt][1]);
            }
        }

        if (kt + 3 < NT) {
            ISSUE(kt + 3, (kt + 3) & 3);
        } else {
            asm volatile("cp.async.commit_group;\n" ::: "memory");
        }
    }
#undef ISSUE

    #pragma unroll
    for (int mt = 0; mt < 4; mt++) {
        int r0 = m0 + wm + mt * 16 + g;
        int r1 = r0 + 8;
        float bv0 = BIAS ? bias[r0] : 0.f;
        float bv1 = BIAS ? bias[r1] : 0.f;
        #pragma unroll
        for (int nt = 0; nt < 4; nt++) {
            int cn = n0 + wn + nt * 8 + 2 * tig;
            float2 y0, y1;
            y0.x = acc[mt][nt][0] + bv0; y0.y = acc[mt][nt][1] + bv0;
            y1.x = acc[mt][nt][2] + bv1; y1.y = acc[mt][nt][3] + bv1;
            if (RELU) {
                y0.x = fmaxf(y0.x, 0.f); y0.y = fmaxf(y0.y, 0.f);
                y1.x = fmaxf(y1.x, 0.f); y1.y = fmaxf(y1.y, 0.f);
            }
            y0.x *= scale; y0.y *= scale;
            y1.x *= scale; y1.y *= scale;
            if (RES) {
                float2 rr0 = *(const float2*)&Resb[(long)r0 * NL + cn];
                float2 rr1 = *(const float2*)&Resb[(long)r1 * NL + cn];
                y0.x += rr0.x; y0.y += rr0.y;
                y1.x += rr1.x; y1.y += rr1.y;
            }
            if (OUTH) {
                __half* Yb = (__half*)Yv + (long)b * bsY;
                *(__half2*)&Yb[(long)r0 * NL + cn] = __floats2half2_rn(y0.x, y0.y);
                *(__half2*)&Yb[(long)r1 * NL + cn] = __floats2half2_rn(y1.x, y1.y);
            } else {
                float* Yb = (float*)Yv + (long)b * bsY;
                *(float2*)&Yb[(long)r0 * NL + cn] = y0;
                *(float2*)&Yb[(long)r1 * NL + cn] = y1;
            }
        }
    }
}

/* ------------------------------------------------------------------ */
/* fp16 flash attention (round-12, passing); R fp32                    */
/* ------------------------------------------------------------------ */
#define HS 72
#define QB (64*HS*2)
#define KVB (2*64*HS*2)
#define ATTN_SMEM (QB + 2*KVB)

__global__ void __launch_bounds__(128, 4)
attn_h_kernel(const __half* __restrict__ Q,
              const __half* __restrict__ KV,
              float* R)
{
    extern __shared__ __half smh[];
    unsigned saQ = (unsigned)__cvta_generic_to_shared(smh);
    __shared__ float corrS[64];

    int qt = blockIdx.x, h = blockIdx.y, b = blockIdx.z;
    int q0 = qt * 64;
    int t    = threadIdx.x;
    int lane = t & 31, w = t >> 5;
    int g    = lane >> 2, tig = lane & 3;
    int wq   = w * 16;

    const __half* Qb = Q  + (long)b * CL_     + (long)(h * 64) * NL + q0;
    const __half* Kb = KV + (long)b * 2 * CL_ + (long)(h * 64) * NL;
    const __half* Vb = KV + (long)b * 2 * CL_ + (long)(512 + h * 64) * NL;

    int ddA = (lane & 7) + ((lane >> 4) & 1) * 8;
    int qqA = wq + ((lane >> 3) & 1) * 8;
    int rowk = (lane & 7) + ((lane >> 3) & 1) * 8;
    int coff = ((lane >> 4) & 1) * 8;

    int dcp = t >> 3;
    int ccp = (t & 7) * 8;

#define ISSUE_KV(KT, BF) {                                                   \
        unsigned kb_ = saQ + QB + (BF) * KVB;                                \
        unsigned vb_ = kb_ + 64 * HS * 2;                                    \
        const __half* gk_ = Kb + (KT) * 64 + ccp;                            \
        const __half* gv_ = Vb + (KT) * 64 + ccp;                            \
        _Pragma("unroll")                                                    \
        for (int i4 = 0; i4 < 4; i4++) {                                     \
            int d_ = i4 * 16 + dcp;                                          \
            cpa16(kb_ + (d_ * HS + ccp) * 2, gk_ + (long)d_ * NL);           \
            cpa16(vb_ + (d_ * HS + ccp) * 2, gv_ + (long)d_ * NL);           \
        }                                                                    \
        asm volatile("cp.async.commit_group;\n" ::: "memory"); }

    ISSUE_KV(0, 0);

    #pragma unroll
    for (int i4 = 0; i4 < 4; i4++) {
        int d_ = i4 * 16 + dcp;
        *(uint4*)&smh[d_ * HS + ccp] = *(const uint4*)&Qb[(long)d_ * NL + ccp];
    }

    float mlo = -1e30f, mhi = -1e30f, llo = 0.f, lhi = 0.f;
    float of[8][4];
    #pragma unroll
    for (int nt = 0; nt < 8; nt++)
        #pragma unroll
        for (int i = 0; i < 4; i++) of[nt][i] = 0.f;

    for (int it = 0; it < 16; it++) {
        asm volatile("cp.async.wait_group 0;\n" ::: "memory");
        __syncthreads();

        int cur = it & 1;
        unsigned saK = saQ + QB + cur * KVB;
        __half*  Ksm = smh + (QB / 2) + cur * (KVB / 2);
        __half*  Vsm = Ksm + 64 * HS;

        if (it + 1 < 16) ISSUE_KV(it + 1, cur ^ 1);

        float sf[8][4];
        #pragma unroll
        for (int nt = 0; nt < 8; nt++)
            #pragma unroll
            for (int i = 0; i < 4; i++) sf[nt][i] = 0.f;

        #pragma unroll
        for (int kk = 0; kk < 64; kk += 16) {
            unsigned a0, a1, a2, a3;
            LDSM4T(a0, a1, a2, a3, saQ + (unsigned)(((kk + ddA) * HS + qqA) * 2));
            unsigned bf[8][2];
            #pragma unroll
            for (int n2 = 0; n2 < 4; n2++)
                LDSM4T(bf[2*n2][0], bf[2*n2][1], bf[2*n2+1][0], bf[2*n2+1][1],
                       saK + (unsigned)(((kk + rowk) * HS + n2 * 16 + coff) * 2));
            #pragma unroll
            for (int nt = 0; nt < 8; nt++)
                MMA_F16(sf[nt][0], sf[nt][1], sf[nt][2], sf[nt][3],
                        a0, a1, a2, a3, bf[nt][0], bf[nt][1]);
        }

        float mx_lo = -1e30f, mx_hi = -1e30f;
        #pragma unroll
        for (int nt = 0; nt < 8; nt++) {
            mx_lo = fmaxf(mx_lo, fmaxf(sf[nt][0], sf[nt][1]));
            mx_hi = fmaxf(mx_hi, fmaxf(sf[nt][2], sf[nt][3]));
        }
        mx_lo = fmaxf(mx_lo, __shfl_xor_sync(0xffffffffu, mx_lo, 1));
        mx_lo = fmaxf(mx_lo, __shfl_xor_sync(0xffffffffu, mx_lo, 2));
        mx_hi = fmaxf(mx_hi, __shfl_xor_sync(0xffffffffu, mx_hi, 1));
        mx_hi = fmaxf(mx_hi, __shfl_xor_sync(0xffffffffu, mx_hi, 2));

        float mn_lo = fmaxf(mlo, mx_lo);
        float mn_hi = fmaxf(mhi, mx_hi);
        float cr_lo = __expf(mlo - mn_lo);
        float cr_hi = __expf(mhi - mn_hi);
        mlo = mn_lo; mhi = mn_hi;

        float ps_lo = 0.f, ps_hi = 0.f;
        #pragma unroll
        for (int nt = 0; nt < 8; nt++) {
            sf[nt][0] = __expf(sf[nt][0] - mn_lo);
            sf[nt][1] = __expf(sf[nt][1] - mn_lo);
            sf[nt][2] = __expf(sf[nt][2] - mn_hi);
            sf[nt][3] = __expf(sf[nt][3] - mn_hi);
            ps_lo += sf[nt][0] + sf[nt][1];
            ps_hi += sf[nt][2] + sf[nt][3];
        }
        ps_lo += __shfl_xor_sync(0xffffffffu, ps_lo, 1);
        ps_lo += __shfl_xor_sync(0xffffffffu, ps_lo, 2);
        ps_hi += __shfl_xor_sync(0xffffffffu, ps_hi, 1);
        ps_hi += __shfl_xor_sync(0xffffffffu, ps_hi, 2);
        llo = llo * cr_lo + ps_lo;
        lhi = lhi * cr_hi + ps_hi;

        if (tig == 0) {
            corrS[wq + g]     = cr_lo;
            corrS[wq + g + 8] = cr_hi;
        }
        __syncthreads();

        #pragma unroll
        for (int nt = 0; nt < 8; nt++) {
            int c0 = nt * 8 + 2 * tig;
            *(__half2*)&Ksm[(wq + g    ) * HS + c0] = __floats2half2_rn(sf[nt][0], sf[nt][1]);
            *(__half2*)&Ksm[(wq + g + 8) * HS + c0] = __floats2half2_rn(sf[nt][2], sf[nt][3]);
        }
        __syncthreads();

        #pragma unroll
        for (int nt = 0; nt < 8; nt++) {
            float c0 = corrS[nt * 8 + 2 * tig];
            float c1 = corrS[nt * 8 + 2 * tig + 1];
            of[nt][0] *= c0; of[nt][1] *= c1;
            of[nt][2] *= c0; of[nt][3] *= c1;
        }

        #pragma unroll
        for (int kk = 0; kk < 64; kk += 16) {
            unsigned a0 = *(const unsigned*)&Vsm[(wq + g    ) * HS + kk + 2*tig];
            unsigned a1 = *(const unsigned*)&Vsm[(wq + g + 8) * HS + kk + 2*tig];
            unsigned a2 = *(const unsigned*)&Vsm[(wq + g    ) * HS + kk + 2*tig + 8];
            unsigned a3 = *(const unsigned*)&Vsm[(wq + g + 8) * HS + kk + 2*tig + 8];
            #pragma unroll
            for (int nt = 0; nt < 8; nt++) {
                unsigned b0 = *(const unsigned*)&Ksm[(nt * 8 + g) * HS + kk + 2*tig];
                unsigned b1 = *(const unsigned*)&Ksm[(nt * 8 + g) * HS + kk + 2*tig + 8];
                MMA_F16(of[nt][0], of[nt][1], of[nt][2], of[nt][3],
                        a0, a1, a2, a3, b0, b1);
            }
        }
    }
#undef ISSUE_KV

    __syncthreads();
    if (tig == 0) {
        corrS[wq + g]     = 1.f / llo;
        corrS[wq + g + 8] = 1.f / lhi;
    }
    __syncthreads();

    float* Rb = R + (long)b * CL_ + (long)(h * 64) * NL;
    #pragma unroll
    for (int nt = 0; nt < 8; nt++) {
        float i0 = corrS[nt * 8 + 2 * tig];
        float i1 = corrS[nt * 8 + 2 * tig + 1];
        int cn = q0 + nt * 8 + 2 * tig;
        int r0 = wq + g, r1 = wq + g + 8;
        float2 rr0 = *(const float2*)&Rb[(long)r0 * NL + cn];
        float2 rr1 = *(const float2*)&Rb[(long)r1 * NL + cn];
        float2 y0, y1;
        y0.x = of[nt][0] * i0 + rr0.x; y0.y = of[nt][1] * i1 + rr0.y;
        y1.x = of[nt][2] * i0 + rr1.x; y1.y = of[nt][3] * i1 + rr1.y;
        *(float2*)&Rb[(long)r0 * NL + cn] = y0;
        *(float2*)&Rb[(long)r1 * NL + cn] = y1;
    }
}

/* ------------------------------------------------------------------ */
extern "C" void kernel_launch(void* const* d_in, const int* in_sizes, int n_in,
                              void* d_out, int out_size)
{
    const float* x    = (const float*)d_in[0];
    const float* ncs  = (const float*)d_in[4];
    const float* ncb  = (const float*)d_in[5];
    const float* dw   = (const float*)d_in[6];
    const float* pww  = (const float*)d_in[7];
    const float* pwb  = (const float*)d_in[8];
    const float* ln1s = (const float*)d_in[9];
    const float* ln1b = (const float*)d_in[10];
    const float* ln2s = (const float*)d_in[11];
    const float* ln2b = (const float*)d_in[12];
    const float* wkv  = (const float*)d_in[13];
    const float* wq   = (const float*)d_in[14];
    const float* f1w  = (const float*)d_in[15];
    const float* f1b  = (const float*)d_in[16];
    const float* f2w  = (const float*)d_in[17];
    const float* f2b  = (const float*)d_in[18];
    float* out = (float*)d_out;

    float *R;
    __half *Wh, *Th, *Th2, *Qh, *KVh;
    cudaGetSymbolAddress((void**)&R,   g_R);
    cudaGetSymbolAddress((void**)&Wh,  g_Wh);
    cudaGetSymbolAddress((void**)&Th,  g_Th);
    cudaGetSymbolAddress((void**)&Th2, g_Th2);
    cudaGetSymbolAddress((void**)&Qh,  g_Qh);
    cudaGetSymbolAddress((void**)&KVh, g_KVh);

    cudaFuncSetAttribute(gemm_h_kernel<true,  true,  true,  false>, cudaFuncAttributeMaxDynamicSharedMemorySize, GEMM_SMEM);
    cudaFuncSetAttribute(gemm_h_kernel<false, false, false, true >, cudaFuncAttributeMaxDynamicSharedMemorySize, GEMM_SMEM);
    cudaFuncSetAttribute(gemm_h_kernel<true,  false, true,  true >, cudaFuncAttributeMaxDynamicSharedMemorySize, GEMM_SMEM);
    cudaFuncSetAttribute(gemm_h_kernel<false, true,  true,  false>, cudaFuncAttributeMaxDynamicSharedMemorySize, GEMM_SMEM);
    cudaFuncSetAttribute(attn_h_kernel, cudaFuncAttributeMaxDynamicSharedMemorySize, ATTN_SMEM);

    dim3 blk(256);

    cvt_h_kernel<<<(4*CC/4 + 255)/256, blk>>>(pww, Wh,          4*CC/4);
    cvt_h_kernel<<<(2*CC/4 + 255)/256, blk>>>(wkv, Wh + 4*CC,   2*CC/4);
    cvt_h_kernel<<<(CC/4   + 255)/256, blk>>>(wq,  Wh + 6*CC,   CC/4);
    cvt_h_kernel<<<(CC/4   + 255)/256, blk>>>(f1w, Wh + 7*CC,   CC/4);
    cvt_h_kernel<<<(CC/4   + 255)/256, blk>>>(f2w, Wh + 8*CC,   CC/4);

    posenc_kernel<<<BCL_ / 256, blk>>>(x, R);

    for (int i = 0; i < 4; i++) {
        dwconv_f_kernel<<<512, blk>>>(R, ncs + i * NC, ncb + i * NC,
                                      dw + (long)i * NC * 7, Th);
        gemm_h_kernel<true, true, true, false><<<dim3(8, 4, NB), blk, GEMM_SMEM>>>(
            Wh + (long)i * CC, Th, R, pwb + i * NC, R, CL_, CL_, CL_, 1.f);
    }

    /* attention */
    ln_fused_kernel<<<512, blk>>>(R, ln1s, ln1b, Th);
    gemm_h_kernel<false, false, false, true><<<dim3(8, 8, NB), blk, GEMM_SMEM>>>(
        Wh + 4*CC, Th, KVh, 0, 0, CL_, 2 * CL_, 0, 1.f);
    gemm_h_kernel<false, false, false, true><<<dim3(8, 4, NB), blk, GEMM_SMEM>>>(
        Wh + 6*CC, Th, Qh, 0, 0, CL_, CL_, 0, 0.125f);

    attn_h_kernel<<<dim3(16, NH, NB), dim3(128), ATTN_SMEM>>>(Qh, KVh, R);

    /* ffn */
    ln_fused_kernel<<<512, blk>>>(R, ln2s, ln2b, Th);
    gemm_h_kernel<true, false, true, true><<<dim3(8, 4, NB), blk, GEMM_SMEM>>>(
        Wh + 7*CC, Th, Th2, f1b, 0, CL_, CL_, 0, 1.f);
    gemm_h_kernel<false, true, true, false><<<dim3(8, 4, NB), blk, GEMM_SMEM>>>(
        Wh + 8*CC, Th2, out, f2b, R, CL_, CL_, CL_, 1.f);
}

// round 15
// speedup vs baseline: 1.2719x; 1.0155x over previous
#include <cuda_runtime.h>
#include <cuda_fp16.h>
#include <math.h>

#define NB 16
#define NC 512
#define NL 1024
#define NH 8
#define CL_ (NC*NL)
#define BCL_ (NB*CL_)
#define CC (NC*NC)

/* ------------------------------------------------------------------ */
__device__ float g_R [BCL_];
__device__ __align__(16) __half g_Wh  [9*CC];
__device__ __align__(16) __half g_Th  [BCL_];
__device__ __align__(16) __half g_Th2 [BCL_];
__device__ __align__(16) __half g_KVQ [3*BCL_];   /* kv (2C) + q (C) */

/* ------------------------------------------------------------------ */
__global__ void cvt_h_kernel(const float* __restrict__ src,
                             __half* __restrict__ dst, int n4, float scale)
{
    int i = blockIdx.x * 256 + threadIdx.x;
    if (i < n4) {
        float4 v = ((const float4*)src)[i];
        ((__half2*)dst)[i*2    ] = __floats2half2_rn(v.x * scale, v.y * scale);
        ((__half2*)dst)[i*2 + 1] = __floats2half2_rn(v.z * scale, v.w * scale);
    }
}

/* ------------------------------------------------------------------ */
__global__ void posenc_kernel(const float* __restrict__ x, float* __restrict__ out)
{
    int idx = blockIdx.x * 256 + threadIdx.x;
    int l = idx & (NL - 1);
    int c = (idx >> 10) & (NC - 1);
    int i = (c < 256) ? c : (c - 256);
    float inv = expf(-(float)i * 0.036118982f);
    float arg = (float)l * inv;
    float sig = (c < 256) ? sinf(arg) : cosf(arg);
    out[idx] = x[idx] + sig;
}

/* ------------------------------------------------------------------ */
__device__ __forceinline__ void block_stats32(const float* __restrict__ Rb,
                                              int l0, int t,
                                              float* smu, float* srs, int joff)
{
    int lane = t & 31, w = t >> 5;
    const float* base = Rb + l0 + lane;
    float s = 0.f, s2 = 0.f;
    for (int c = w; c < NC; c += 8) {
        float v = base[c * NL];
        s += v; s2 += v * v;
    }
    __shared__ float sh1[8][33], sh2[8][33];
    sh1[w][lane] = s; sh2[w][lane] = s2;
    __syncthreads();
    if (t < 32) {
        float a = 0.f, q = 0.f;
        #pragma unroll
        for (int ww = 0; ww < 8; ww++) { a += sh1[ww][t]; q += sh2[ww][t]; }
        float m   = a * (1.f / NC);
        float var = q * (1.f / NC) - m * m;
        smu[joff + t] = m;
        srs[joff + t] = rsqrtf(var + 1e-5f);
    }
}

/* ------------------------------------------------------------------ */
__global__ void __launch_bounds__(256, 4)
ln_fused_kernel(const float* __restrict__ R,
                const float* __restrict__ sc,
                const float* __restrict__ bi,
                __half* __restrict__ out)
{
    int tile = blockIdx.x;
    int b  = tile >> 5;
    int l0 = (tile & 31) << 5;
    int t  = threadIdx.x;

    __shared__ float smu[32], srs[32];
    const float* Rb = R + (long)b * CL_;
    block_stats32(Rb, l0, t, smu, srs, 0);
    __syncthreads();

    __half* ob = (__half*)out + (long)b * CL_;
    for (int i = t; i < NC * 16; i += 256) {
        int c  = i >> 4;
        int lj = (i & 15) * 2;
        long off = (long)c * NL + l0 + lj;
        float2 v = *(const float2*)&Rb[off];
        float s  = sc[c], bb = bi[c];
        float y0 = (v.x - smu[lj])     * srs[lj]     * s + bb;
        float y1 = (v.y - smu[lj + 1]) * srs[lj + 1] * s + bb;
        *(__half2*)&ob[off] = __floats2half2_rn(y0, y1);
    }
}

/* ------------------------------------------------------------------ */
__global__ void __launch_bounds__(256, 4)
dwconv_f_kernel(const float* __restrict__ R,
                const float* __restrict__ sc,
                const float* __restrict__ bi,
                const float* __restrict__ w7,
                __half* __restrict__ T)
{
    int tile = blockIdx.x;
    int b  = tile >> 5;
    int l0 = (tile & 31) << 5;
    int t  = threadIdx.x;
    int lane = t & 31, w = t >> 5;

    __shared__ float smu[38], srs[38];
    const float* Rb = R + (long)b * CL_;

    block_stats32(Rb, l0, t, smu, srs, 3);

    if (w >= 1 && w <= 6) {
        int li = (w <= 3) ? (l0 - 4 + w) : (l0 + 28 + w);
        if (li >= 0 && li < NL) {
            const float* p = Rb + li;
            float a = 0.f, q = 0.f;
            for (int c = lane; c < NC; c += 32) {
                float v = p[c * NL];
                a += v; q += v * v;
            }
            #pragma unroll
            for (int off = 16; off > 0; off >>= 1) {
                a += __shfl_xor_sync(0xffffffffu, a, off);
                q += __shfl_xor_sync(0xffffffffu, q, off);
            }
            if (lane == 0) {
                float m   = a * (1.f / NC);
                float var = q * (1.f / NC) - m * m;
                int j = li - l0 + 3;
                smu[j] = m;
                srs[j] = rsqrtf(var + 1e-5f);
            }
        }
    }
    __syncthreads();

    __half* Tb = (__half*)T + (long)b * CL_;
    for (int i = t; i < NC * 32; i += 256) {
        int c = i >> 5;
        int l = l0 + (i & 31);
        const float* r = Rb + (long)c * NL;
        float s  = sc[c], bb = bi[c];
        float acc = 0.f;
        #pragma unroll
        for (int k = 0; k < 7; k++) {
            int ll = l + k - 3;
            if (ll >= 0 && ll < NL) {
                int j = ll - l0 + 3;
                float v = (r[ll] - smu[j]) * srs[j] * s + bb;
                acc += w7[c * 7 + k] * v;
            }
        }
        Tb[(long)c * NL + l] = __float2half(acc);
    }
}

/* ------------------------------------------------------------------ */
#define MMA_F16(d0,d1,d2,d3,a0,a1,a2,a3,b0,b1)                               \
    asm volatile(                                                            \
        "mma.sync.aligned.m16n8k16.row.col.f32.f16.f16.f32 "                 \
        "{%0,%1,%2,%3}, {%4,%5,%6,%7}, {%8,%9}, {%0,%1,%2,%3};\n"            \
        : "+f"(d0), "+f"(d1), "+f"(d2), "+f"(d3)                             \
        : "r"(a0), "r"(a1), "r"(a2), "r"(a3), "r"(b0), "r"(b1))

#define LDSM4T(r0,r1,r2,r3,addr)                                             \
    asm volatile("ldmatrix.sync.aligned.m8n8.x4.trans.shared.b16 "           \
                 "{%0,%1,%2,%3}, [%4];"                                      \
                 : "=r"(r0), "=r"(r1), "=r"(r2), "=r"(r3) : "r"(addr))

#define LDSM4(r0,r1,r2,r3,addr)                                              \
    asm volatile("ldmatrix.sync.aligned.m8n8.x4.shared.b16 "                 \
                 "{%0,%1,%2,%3}, [%4];"                                      \
                 : "=r"(r0), "=r"(r1), "=r"(r2), "=r"(r3) : "r"(addr))

__device__ __forceinline__ void cpa16(unsigned saddr, const void* gaddr)
{
    asm volatile("cp.async.cg.shared.global [%0], [%1], 16;\n"
                 :: "r"(saddr), "l"(gaddr));
}

/* ------------------------------------------------------------------ */
/* fp16 batched GEMM: round-12 mainloop + smem-staged coalesced epilog */
/* ------------------------------------------------------------------ */
#define SAH 40
#define SBH 136
#define ASZB (128*SAH*2)
#define BSZB (32*SBH*2)
#define STAGES 4
#define GEMM_SMEM (STAGES*(ASZB+BSZB))   /* 75776 B; epilogue tile 128*132*4 = 67584 B fits */
#define EPS 132

template<bool RELU, bool RES, bool BIAS, bool OUTH>
__global__ void __launch_bounds__(256, 2)
gemm_h_kernel(const __half* __restrict__ W,
              const __half* __restrict__ X,
              void*                      Yv,
              const float* __restrict__ bias,
              const float*              res,
              long bsX, long bsY, long bsRes, float scale)
{
    const int Kd = NC;
    const int NT = Kd / 32;
    int b  = blockIdx.z;
    int n0 = blockIdx.x * 128;
    int m0 = blockIdx.y * 128;

    const __half* Xb   = X + (long)b * bsX;
    const float*  Resb = RES ? (res + (long)b * bsRes) : (const float*)0;

    extern __shared__ __half gsm[];
    unsigned saA = (unsigned)__cvta_generic_to_shared(gsm);
    unsigned saB = saA + STAGES * ASZB;

    int t    = threadIdx.x;
    int lane = t & 31, w = t >> 5;
    int g    = lane >> 2, tig = lane & 3;
    int wm   = (w >> 2) * 64;
    int wn   = (w & 3) * 32;

    int rA  = t & 127;
    int cAh = (t >> 7) * 8;
    int kB  = t >> 3;
    int cBh = (t & 7) * 8;

    unsigned sA = saA + (rA * SAH + cAh) * 2;
    unsigned sB = saB + (kB * SBH + cBh) * 2;
    const __half* gA = W  + (long)(m0 + rA) * Kd + cAh;
    const __half* gB = Xb + (long)kB * NL + n0 + cBh;

    int rowk = (lane & 7) + ((lane >> 3) & 1) * 8;
    int coff = ((lane >> 4) & 1) * 8;

    float acc[4][4][4];
    #pragma unroll
    for (int mt = 0; mt < 4; mt++)
        #pragma unroll
        for (int nt = 0; nt < 4; nt++)
            #pragma unroll
            for (int i = 0; i < 4; i++) acc[mt][nt][i] = 0.f;

#define ISSUE(KT, STG) {                                                  \
        unsigned a_ = sA + (STG) * ASZB;                                  \
        const __half* ga_ = gA + (KT) * 32;                               \
        cpa16(a_,      ga_);                                              \
        cpa16(a_ + 32, ga_ + 16);                                         \
        unsigned b_ = sB + (STG) * BSZB;                                  \
        const __half* gb_ = gB + (long)(KT) * 32 * NL;                    \
        cpa16(b_,       gb_);                                             \
        cpa16(b_ + 128, gb_ + 64);                                        \
        asm volatile("cp.async.commit_group;\n" ::: "memory"); }

    ISSUE(0, 0);
    ISSUE(1, 1);
    ISSUE(2, 2);

    for (int kt = 0; kt < NT; kt++) {
        asm volatile("cp.async.wait_group 2;\n" ::: "memory");
        __syncthreads();

        int cur = kt & 3;
        unsigned aBase = saA + cur * ASZB;
        unsigned bBase = saB + cur * BSZB;

        #pragma unroll
        for (int kk = 0; kk < 32; kk += 16) {
            unsigned bf[4][2];
            unsigned bb = bBase + (unsigned)(((kk + rowk) * SBH + wn + coff) * 2);
            LDSM4T(bf[0][0], bf[0][1], bf[1][0], bf[1][1], bb);
            LDSM4T(bf[2][0], bf[2][1], bf[3][0], bf[3][1], bb + 32);

            #pragma unroll
            for (int mt = 0; mt < 4; mt++) {
                unsigned a0, a1, a2, a3;
                LDSM4(a0, a1, a2, a3,
                      aBase + (unsigned)(((wm + mt * 16 + rowk) * SAH + kk + coff) * 2));
                #pragma unroll
                for (int nt = 0; nt < 4; nt++)
                    MMA_F16(acc[mt][nt][0], acc[mt][nt][1],
                            acc[mt][nt][2], acc[mt][nt][3],
                            a0, a1, a2, a3, bf[nt][0], bf[nt][1]);
            }
        }

        if (kt + 3 < NT) {
            ISSUE(kt + 3, (kt + 3) & 3);
        } else {
            asm volatile("cp.async.commit_group;\n" ::: "memory");
        }
    }
#undef ISSUE

    /* ---- epilogue: stage accs in smem, then coalesced streaming ---- */
    __syncthreads();                       /* all LDSM reads of smem done */
    float* sm = (float*)gsm;               /* 128 x EPS fp32 tile */

    #pragma unroll
    for (int mt = 0; mt < 4; mt++) {
        int r0 = wm + mt * 16 + g;
        int r1 = r0 + 8;
        #pragma unroll
        for (int nt = 0; nt < 4; nt++) {
            int cn = wn + nt * 8 + 2 * tig;
            *(float2*)&sm[r0 * EPS + cn] = make_float2(acc[mt][nt][0], acc[mt][nt][1]);
            *(float2*)&sm[r1 * EPS + cn] = make_float2(acc[mt][nt][2], acc[mt][nt][3]);
        }
    }
    __syncthreads();

    #pragma unroll
    for (int it = 0; it < 16; it++) {
        int idx = it * 256 + t;
        int r  = idx >> 5;                 /* 0..127 */
        int c4 = (idx & 31) * 4;           /* 0..124 */
        float4 y = *(float4*)&sm[r * EPS + c4];
        if (BIAS) {
            float bv = bias[m0 + r];
            y.x += bv; y.y += bv; y.z += bv; y.w += bv;
        }
        if (RELU) {
            y.x = fmaxf(y.x, 0.f); y.y = fmaxf(y.y, 0.f);
            y.z = fmaxf(y.z, 0.f); y.w = fmaxf(y.w, 0.f);
        }
        y.x *= scale; y.y *= scale; y.z *= scale; y.w *= scale;
        long go = (long)(m0 + r) * NL + n0 + c4;
        if (RES) {
            float4 rr = *(const float4*)&Resb[go];
            y.x += rr.x; y.y += rr.y; y.z += rr.z; y.w += rr.w;
        }
        if (OUTH) {
            __half* Yb = (__half*)Yv + (long)b * bsY;
            __half2 h01 = __floats2half2_rn(y.x, y.y);
            __half2 h23 = __floats2half2_rn(y.z, y.w);
            uint2 u;
            u.x = *(unsigned*)&h01;
            u.y = *(unsigned*)&h23;
            *(uint2*)&Yb[go] = u;
        } else {
            float* Yb = (float*)Yv + (long)b * bsY;
            *(float4*)&Yb[go] = y;
        }
    }
}

/* ------------------------------------------------------------------ */
/* fp16 flash attention (round-12, passing); KVQ merged buffer         */
/* ------------------------------------------------------------------ */
#define HS 72
#define QB (64*HS*2)
#define KVB (2*64*HS*2)
#define ATTN_SMEM (QB + 2*KVB)

__global__ void __launch_bounds__(128, 4)
attn_h_kernel(const __half* __restrict__ KVQ, float* R)
{
    extern __shared__ __half smh[];
    unsigned saQ = (unsigned)__cvta_generic_to_shared(smh);
    __shared__ float corrS[64];

    int qt = blockIdx.x, h = blockIdx.y, b = blockIdx.z;
    int q0 = qt * 64;
    int t    = threadIdx.x;
    int lane = t & 31, w = t >> 5;
    int g    = lane >> 2, tig = lane & 3;
    int wq   = w * 16;

    const __half* base = KVQ + (long)b * 3 * CL_;
    const __half* Kb = base + (long)(h * 64) * NL;
    const __half* Vb = base + (long)(512 + h * 64) * NL;
    const __half* Qb = base + (long)(1024 + h * 64) * NL + q0;

    int ddA = (lane & 7) + ((lane >> 4) & 1) * 8;
    int qqA = wq + ((lane >> 3) & 1) * 8;
    int rowk = (lane & 7) + ((lane >> 3) & 1) * 8;
    int coff = ((lane >> 4) & 1) * 8;

    int dcp = t >> 3;
    int ccp = (t & 7) * 8;

#define ISSUE_KV(KT, BF) {                                                   \
        unsigned kb_ = saQ + QB + (BF) * KVB;                                \
        unsigned vb_ = kb_ + 64 * HS * 2;                                    \
        const __half* gk_ = Kb + (KT) * 64 + ccp;                            \
        const __half* gv_ = Vb + (KT) * 64 + ccp;                            \
        _Pragma("unroll")                                                    \
        for (int i4 = 0; i4 < 4; i4++) {                                     \
            int d_ = i4 * 16 + dcp;                                          \
            cpa16(kb_ + (d_ * HS + ccp) * 2, gk_ + (long)d_ * NL);           \
            cpa16(vb_ + (d_ * HS + ccp) * 2, gv_ + (long)d_ * NL);           \
        }                                                                    \
        asm volatile("cp.async.commit_group;\n" ::: "memory"); }

    ISSUE_KV(0, 0);

    #pragma unroll
    for (int i4 = 0; i4 < 4; i4++) {
        int d_ = i4 * 16 + dcp;
        *(uint4*)&smh[d_ * HS + ccp] = *(const uint4*)&Qb[(long)d_ * NL + ccp];
    }

    float mlo = -1e30f, mhi = -1e30f, llo = 0.f, lhi = 0.f;
    float of[8][4];
    #pragma unroll
    for (int nt = 0; nt < 8; nt++)
        #pragma unroll
        for (int i = 0; i < 4; i++) of[nt][i] = 0.f;

    for (int it = 0; it < 16; it++) {
        asm volatile("cp.async.wait_group 0;\n" ::: "memory");
        __syncthreads();

        int cur = it & 1;
        unsigned saK = saQ + QB + cur * KVB;
        __half*  Ksm = smh + (QB / 2) + cur * (KVB / 2);
        __half*  Vsm = Ksm + 64 * HS;

        if (it + 1 < 16) ISSUE_KV(it + 1, cur ^ 1);

        float sf[8][4];
        #pragma unroll
        for (int nt = 0; nt < 8; nt++)
            #pragma unroll
            for (int i = 0; i < 4; i++) sf[nt][i] = 0.f;

        #pragma unroll
        for (int kk = 0; kk < 64; kk += 16) {
            unsigned a0, a1, a2, a3;
            LDSM4T(a0, a1, a2, a3, saQ + (unsigned)(((kk + ddA) * HS + qqA) * 2));
            unsigned bf[8][2];
            #pragma unroll
            for (int n2 = 0; n2 < 4; n2++)
                LDSM4T(bf[2*n2][0], bf[2*n2][1], bf[2*n2+1][0], bf[2*n2+1][1],
                       saK + (unsigned)(((kk + rowk) * HS + n2 * 16 + coff) * 2));
            #pragma unroll
            for (int nt = 0; nt < 8; nt++)
                MMA_F16(sf[nt][0], sf[nt][1], sf[nt][2], sf[nt][3],
                        a0, a1, a2, a3, bf[nt][0], bf[nt][1]);
        }

        float mx_lo = -1e30f, mx_hi = -1e30f;
        #pragma unroll
        for (int nt = 0; nt < 8; nt++) {
            mx_lo = fmaxf(mx_lo, fmaxf(sf[nt][0], sf[nt][1]));
            mx_hi = fmaxf(mx_hi, fmaxf(sf[nt][2], sf[nt][3]));
        }
        mx_lo = fmaxf(mx_lo, __shfl_xor_sync(0xffffffffu, mx_lo, 1));
        mx_lo = fmaxf(mx_lo, __shfl_xor_sync(0xffffffffu, mx_lo, 2));
        mx_hi = fmaxf(mx_hi, __shfl_xor_sync(0xffffffffu, mx_hi, 1));
        mx_hi = fmaxf(mx_hi, __shfl_xor_sync(0xffffffffu, mx_hi, 2));

        float mn_lo = fmaxf(mlo, mx_lo);
        float mn_hi = fmaxf(mhi, mx_hi);
        float cr_lo = __expf(mlo - mn_lo);
        float cr_hi = __expf(mhi - mn_hi);
        mlo = mn_lo; mhi = mn_hi;

        float ps_lo = 0.f, ps_hi = 0.f;
        #pragma unroll
        for (int nt = 0; nt < 8; nt++) {
            sf[nt][0] = __expf(sf[nt][0] - mn_lo);
            sf[nt][1] = __expf(sf[nt][1] - mn_lo);
            sf[nt][2] = __expf(sf[nt][2] - mn_hi);
            sf[nt][3] = __expf(sf[nt][3] - mn_hi);
            ps_lo += sf[nt][0] + sf[nt][1];
            ps_hi += sf[nt][2] + sf[nt][3];
        }
        ps_lo += __shfl_xor_sync(0xffffffffu, ps_lo, 1);
        ps_lo += __shfl_xor_sync(0xffffffffu, ps_lo, 2);
        ps_hi += __shfl_xor_sync(0xffffffffu, ps_hi, 1);
        ps_hi += __shfl_xor_sync(0xffffffffu, ps_hi, 2);
        llo = llo * cr_lo + ps_lo;
        lhi = lhi * cr_hi + ps_hi;

        if (tig == 0) {
            corrS[wq + g]     = cr_lo;
            corrS[wq + g + 8] = cr_hi;
        }
        __syncthreads();

        #pragma unroll
        for (int nt = 0; nt < 8; nt++) {
            int c0 = nt * 8 + 2 * tig;
            *(__half2*)&Ksm[(wq + g    ) * HS + c0] = __floats2half2_rn(sf[nt][0], sf[nt][1]);
            *(__half2*)&Ksm[(wq + g + 8) * HS + c0] = __floats2half2_rn(sf[nt][2], sf[nt][3]);
        }
        __syncthreads();

        #pragma unroll
        for (int nt = 0; nt < 8; nt++) {
            float c0 = corrS[nt * 8 + 2 * tig];
            float c1 = corrS[nt * 8 + 2 * tig + 1];
            of[nt][0] *= c0; of[nt][1] *= c1;
            of[nt][2] *= c0; of[nt][3] *= c1;
        }

        #pragma unroll
        for (int kk = 0; kk < 64; kk += 16) {
            unsigned a0 = *(const unsigned*)&Vsm[(wq + g    ) * HS + kk + 2*tig];
            unsigned a1 = *(const unsigned*)&Vsm[(wq + g + 8) * HS + kk + 2*tig];
            unsigned a2 = *(const unsigned*)&Vsm[(wq + g    ) * HS + kk + 2*tig + 8];
            unsigned a3 = *(const unsigned*)&Vsm[(wq + g + 8) * HS + kk + 2*tig + 8];
            #pragma unroll
            for (int nt = 0; nt < 8; nt++) {
                unsigned b0 = *(const unsigned*)&Ksm[(nt * 8 + g) * HS + kk + 2*tig];
                unsigned b1 = *(const unsigned*)&Ksm[(nt * 8 + g) * HS + kk + 2*tig + 8];
                MMA_F16(of[nt][0], of[nt][1], of[nt][2], of[nt][3],
                        a0, a1, a2, a3, b0, b1);
            }
        }
    }
#undef ISSUE_KV

    __syncthreads();
    if (tig == 0) {
        corrS[wq + g]     = 1.f / llo;
        corrS[wq + g + 8] = 1.f / lhi;
    }
    __syncthreads();

    float* Rb = R + (long)b * CL_ + (long)(h * 64) * NL;
    #pragma unroll
    for (int nt = 0; nt < 8; nt++) {
        float i0 = corrS[nt * 8 + 2 * tig];
        float i1 = corrS[nt * 8 + 2 * tig + 1];
        int cn = q0 + nt * 8 + 2 * tig;
        int r0 = wq + g, r1 = wq + g + 8;
        float2 rr0 = *(const float2*)&Rb[(long)r0 * NL + cn];
        float2 rr1 = *(const float2*)&Rb[(long)r1 * NL + cn];
        float2 y0, y1;
        y0.x = of[nt][0] * i0 + rr0.x; y0.y = of[nt][1] * i1 + rr0.y;
        y1.x = of[nt][2] * i0 + rr1.x; y1.y = of[nt][3] * i1 + rr1.y;
        *(float2*)&Rb[(long)r0 * NL + cn] = y0;
        *(float2*)&Rb[(long)r1 * NL + cn] = y1;
    }
}

/* ------------------------------------------------------------------ */
extern "C" void kernel_launch(void* const* d_in, const int* in_sizes, int n_in,
                              void* d_out, int out_size)
{
    const float* x    = (const float*)d_in[0];
    const float* ncs  = (const float*)d_in[4];
    const float* ncb  = (const float*)d_in[5];
    const float* dw   = (const float*)d_in[6];
    const float* pww  = (const float*)d_in[7];
    const float* pwb  = (const float*)d_in[8];
    const float* ln1s = (const float*)d_in[9];
    const float* ln1b = (const float*)d_in[10];
    const float* ln2s = (const float*)d_in[11];
    const float* ln2b = (const float*)d_in[12];
    const float* wkv  = (const float*)d_in[13];
    const float* wq   = (const float*)d_in[14];
    const float* f1w  = (const float*)d_in[15];
    const float* f1b  = (const float*)d_in[16];
    const float* f2w  = (const float*)d_in[17];
    const float* f2b  = (const float*)d_in[18];
    float* out = (float*)d_out;

    float *R;
    __half *Wh, *Th, *Th2, *KVQ;
    cudaGetSymbolAddress((void**)&R,   g_R);
    cudaGetSymbolAddress((void**)&Wh,  g_Wh);
    cudaGetSymbolAddress((void**)&Th,  g_Th);
    cudaGetSymbolAddress((void**)&Th2, g_Th2);
    cudaGetSymbolAddress((void**)&KVQ, g_KVQ);

    cudaFuncSetAttribute(gemm_h_kernel<true,  true,  true,  false>, cudaFuncAttributeMaxDynamicSharedMemorySize, GEMM_SMEM);
    cudaFuncSetAttribute(gemm_h_kernel<false, false, false, true >, cudaFuncAttributeMaxDynamicSharedMemorySize, GEMM_SMEM);
    cudaFuncSetAttribute(gemm_h_kernel<true,  false, true,  true >, cudaFuncAttributeMaxDynamicSharedMemorySize, GEMM_SMEM);
    cudaFuncSetAttribute(gemm_h_kernel<false, true,  true,  false>, cudaFuncAttributeMaxDynamicSharedMemorySize, GEMM_SMEM);
    cudaFuncSetAttribute(attn_h_kernel, cudaFuncAttributeMaxDynamicSharedMemorySize, ATTN_SMEM);

    dim3 blk(256);

    /* weight conversions; 0.125 q-scale folded into wq */
    cvt_h_kernel<<<(4*CC/4 + 255)/256, blk>>>(pww, Wh,          4*CC/4, 1.f);
    cvt_h_kernel<<<(2*CC/4 + 255)/256, blk>>>(wkv, Wh + 4*CC,   2*CC/4, 1.f);
    cvt_h_kernel<<<(CC/4   + 255)/256, blk>>>(wq,  Wh + 6*CC,   CC/4,   0.125f);
    cvt_h_kernel<<<(CC/4   + 255)/256, blk>>>(f1w, Wh + 7*CC,   CC/4,   1.f);
    cvt_h_kernel<<<(CC/4   + 255)/256, blk>>>(f2w, Wh + 8*CC,   CC/4,   1.f);

    posenc_kernel<<<BCL_ / 256, blk>>>(x, R);

    for (int i = 0; i < 4; i++) {
        dwconv_f_kernel<<<512, blk>>>(R, ncs + i * NC, ncb + i * NC,
                                      dw + (long)i * NC * 7, Th);
        gemm_h_kernel<true, true, true, false><<<dim3(8, 4, NB), blk, GEMM_SMEM>>>(
            Wh + (long)i * CC, Th, R, pwb + i * NC, R, CL_, CL_, CL_, 1.f);
    }

    /* attention: merged kv+q GEMM (1536 output rows) */
    ln_fused_kernel<<<512, blk>>>(R, ln1s, ln1b, Th);
    gemm_h_kernel<false, false, false, true><<<dim3(8, 12, NB), blk, GEMM_SMEM>>>(
        Wh + 4*CC, Th, KVQ, 0, 0, CL_, 3 * CL_, 0, 1.f);

    attn_h_kernel<<<dim3(16, NH, NB), dim3(128), ATTN_SMEM>>>(KVQ, R);

    /* ffn */
    ln_fused_kernel<<<512, blk>>>(R, ln2s, ln2b, Th);
    gemm_h_kernel<true, false, true, true><<<dim3(8, 4, NB), blk, GEMM_SMEM>>>(
        Wh + 7*CC, Th, Th2, f1b, 0, CL_, CL_, 0, 1.f);
    gemm_h_kernel<false, true, true, false><<<dim3(8, 4, NB), blk, GEMM_SMEM>>>(
        Wh + 8*CC, Th2, out, f2b, R, CL_, CL_, CL_, 1.f);
}